// round 5
// baseline (speedup 1.0000x reference)
#include <cuda_runtime.h>
#include <cstddef>

#define NA 20000
#define NP 40000
#define EE 400000
#define HID 128
#define NCLS 16

// ----------------------------- scratch (static device globals; no runtime alloc) --
__device__ float g_auth0[NA * HID];
__device__ float g_auth1[NA * HID];
__device__ float g_pap0[NP * HID];
__device__ float g_pap1[NP * HID];
__device__ float g_xh_a[NA * HID];
__device__ float g_xh_p[NP * HID];
__device__ float g_asrc[NP * 8];
__device__ float g_adst[NP * 8];
__device__ float g_escr[(size_t)EE * 8];
__device__ float g_denom[NP * 8];
__device__ float g_aggP0[NP * HID];
__device__ float g_aggP1[NP * HID];
__device__ float g_colsum[2 * HID];
__device__ float g_attn[2];
__device__ float g_zbias[HID];   // zero-initialized

// ----------------------------- helpers -------------------------------------------
__device__ __forceinline__ void atomic_add_f4(float4* addr, float4 v) {
#if __CUDA_ARCH__ >= 900
    atomicAdd(addr, v);   // vector red.global.add.v4.f32
#else
    float* f = (float*)addr;
    atomicAdd(f + 0, v.x); atomicAdd(f + 1, v.y);
    atomicAdd(f + 2, v.z); atomicAdd(f + 3, v.w);
#endif
}

// ----------------------------- SGEMM: C[Mx128] = A[MxK] @ B[Kx128] (+bias) --------
// TANH_COLSUM=1: instead of storing C, compute tanh(acc+bias) and accumulate
// per-column sums into colsum[128] (for the semantic-attention score).
template <int TANH_COLSUM>
__global__ __launch_bounds__(256)
void sgemm_k(const float* __restrict__ A, const float* __restrict__ B,
             const float* __restrict__ bias, float* __restrict__ C,
             float* __restrict__ colsum, int M, int K)
{
    __shared__ alignas(16) float As[8][128];
    __shared__ alignas(16) float Bs[8][128];

    const int tid = threadIdx.x;
    const int tx = tid & 15;         // 16 col groups of 8
    const int ty = tid >> 4;         // 16 row groups of 8
    const int block_row = blockIdx.x * 128;

    const int a_row = tid >> 1;          // 0..127
    const int a_col = (tid & 1) * 4;     // 0 or 4
    const int b_row = tid >> 5;          // 0..7
    const int b_col = (tid & 31) * 4;    // 0..124

    float acc[8][8];
#pragma unroll
    for (int i = 0; i < 8; i++)
#pragma unroll
        for (int j = 0; j < 8; j++) acc[i][j] = 0.f;

    for (int k0 = 0; k0 < K; k0 += 8) {
        const int gr = block_row + a_row;
        float4 av = make_float4(0.f, 0.f, 0.f, 0.f);
        if (gr < M) av = *(const float4*)(A + (size_t)gr * K + k0 + a_col);
        As[a_col + 0][a_row] = av.x;
        As[a_col + 1][a_row] = av.y;
        As[a_col + 2][a_row] = av.z;
        As[a_col + 3][a_row] = av.w;
        *(float4*)&Bs[b_row][b_col] =
            *(const float4*)(B + (size_t)(k0 + b_row) * 128 + b_col);
        __syncthreads();

#pragma unroll
        for (int k = 0; k < 8; k++) {
            float4 a0 = *(const float4*)&As[k][ty * 8];
            float4 a1 = *(const float4*)&As[k][ty * 8 + 4];
            float4 b0 = *(const float4*)&Bs[k][tx * 8];
            float4 b1 = *(const float4*)&Bs[k][tx * 8 + 4];
            float ar[8] = {a0.x, a0.y, a0.z, a0.w, a1.x, a1.y, a1.z, a1.w};
            float br[8] = {b0.x, b0.y, b0.z, b0.w, b1.x, b1.y, b1.z, b1.w};
#pragma unroll
            for (int i = 0; i < 8; i++)
#pragma unroll
                for (int j = 0; j < 8; j++)
                    acc[i][j] = fmaf(ar[i], br[j], acc[i][j]);
        }
        __syncthreads();
    }

    float bc[8];
#pragma unroll
    for (int j = 0; j < 8; j++) bc[j] = __ldg(&bias[tx * 8 + j]);

    if constexpr (TANH_COLSUM) {
        __shared__ float red[128];
        if (tid < 128) red[tid] = 0.f;
        __syncthreads();
        float cs[8];
#pragma unroll
        for (int j = 0; j < 8; j++) cs[j] = 0.f;
#pragma unroll
        for (int i = 0; i < 8; i++) {
            const int r = block_row + ty * 8 + i;
            if (r < M) {
#pragma unroll
                for (int j = 0; j < 8; j++)
                    cs[j] += tanhf(acc[i][j] + bc[j]);
            }
        }
#pragma unroll
        for (int j = 0; j < 8; j++) atomicAdd(&red[tx * 8 + j], cs[j]);
        __syncthreads();
        if (tid < 128) atomicAdd(&colsum[tid], red[tid]);
    } else {
#pragma unroll
        for (int i = 0; i < 8; i++) {
            const int r = block_row + ty * 8 + i;
            if (r < M) {
                float4 v0 = make_float4(acc[i][0] + bc[0], acc[i][1] + bc[1],
                                        acc[i][2] + bc[2], acc[i][3] + bc[3]);
                float4 v1 = make_float4(acc[i][4] + bc[4], acc[i][5] + bc[5],
                                        acc[i][6] + bc[6], acc[i][7] + bc[7]);
                *(float4*)(C + (size_t)r * 128 + tx * 8)     = v0;
                *(float4*)(C + (size_t)r * 128 + tx * 8 + 4) = v1;
            }
        }
    }
}

// ----------------------------- per-node attention scores --------------------------
// out[n*8+h] = dot(xh[n, h*16 : h*16+16], att[h*16 : h*16+16])
__global__ void att_scores_k(const float* __restrict__ xh, const float* __restrict__ att,
                             float* __restrict__ out, int N)
{
    const int t = blockIdx.x * blockDim.x + threadIdx.x;
    if (t >= N * 8) return;
    const int n = t >> 3, h = t & 7;
    const float4* xr = (const float4*)(xh + (size_t)n * HID + h * 16);
    const float4* ar = (const float4*)(att + h * 16);
    float s = 0.f;
#pragma unroll
    for (int i = 0; i < 4; i++) {
        float4 a = __ldg(&xr[i]);
        float4 b = __ldg(&ar[i]);
        s += a.x * b.x + a.y * b.y + a.z * b.z + a.w * b.w;
    }
    out[t] = s;
}

// ----------------------------- edge pass A: e=exp(leakyrelu(as+ad)); denom += e ----
// (segment-softmax max-subtraction elided: scores are O(1), result identical)
__global__ void edge_passA(const int* __restrict__ ei, const float* __restrict__ asrc,
                           const float* __restrict__ adst, float* __restrict__ escr,
                           float* __restrict__ denom)
{
    const int e = blockIdx.x * blockDim.x + threadIdx.x;
    if (e >= EE) return;
    const int si = __ldg(&ei[e]);
    const int di = __ldg(&ei[EE + e]);
    const float4* sp = (const float4*)(asrc + (size_t)si * 8);
    const float4* dp = (const float4*)(adst + (size_t)di * 8);
    float4 s0 = __ldg(&sp[0]), s1 = __ldg(&sp[1]);
    float4 d0 = __ldg(&dp[0]), d1 = __ldg(&dp[1]);
    float v[8] = {s0.x + d0.x, s0.y + d0.y, s0.z + d0.z, s0.w + d0.w,
                  s1.x + d1.x, s1.y + d1.y, s1.z + d1.z, s1.w + d1.w};
#pragma unroll
    for (int i = 0; i < 8; i++) {
        float a = v[i];
        a = (a >= 0.f) ? a : 0.2f * a;   // leaky_relu
        v[i] = __expf(a);
    }
    float4 e0 = make_float4(v[0], v[1], v[2], v[3]);
    float4 e1 = make_float4(v[4], v[5], v[6], v[7]);
    ((float4*)escr)[(size_t)e * 2]     = e0;
    ((float4*)escr)[(size_t)e * 2 + 1] = e1;
    atomic_add_f4((float4*)(denom + (size_t)di * 8),     e0);
    atomic_add_f4((float4*)(denom + (size_t)di * 8) + 1, e1);
}

// ----------------------------- edge pass B: agg[di] += xh[si] * (e/denom) ----------
// one warp per edge; lane l covers floats [4l, 4l+4); head h = l>>2
__global__ void edge_passB(const int* __restrict__ ei, const float* __restrict__ xh_src,
                           const float* __restrict__ escr, const float* __restrict__ denom,
                           float* __restrict__ agg)
{
    const int gt = blockIdx.x * blockDim.x + threadIdx.x;
    const int e = gt >> 5;
    if (e >= EE) return;
    const int lane = gt & 31;
    const int si = __ldg(&ei[e]);
    const int di = __ldg(&ei[EE + e]);
    const int h = lane >> 2;
    const float w = __ldg(&escr[(size_t)e * 8 + h]) /
                    (__ldg(&denom[(size_t)di * 8 + h]) + 1e-16f);
    float4 v = __ldg(((const float4*)xh_src) + (size_t)si * 32 + lane);
    v.x *= w; v.y *= w; v.z *= w; v.w *= w;
    atomic_add_f4(((float4*)agg) + (size_t)di * 32 + lane, v);
}

// ----------------------------- elementwise ----------------------------------------
__global__ void relu4_k(float4* p, int n4)
{
    const int i = blockIdx.x * blockDim.x + threadIdx.x;
    if (i >= n4) return;
    float4 v = p[i];
    v.x = fmaxf(v.x, 0.f); v.y = fmaxf(v.y, 0.f);
    v.z = fmaxf(v.z, 0.f); v.w = fmaxf(v.w, 0.f);
    p[i] = v;
}

__global__ void combine_k(float4* __restrict__ out, const float4* __restrict__ s0,
                          const float4* __restrict__ s1, const float* __restrict__ attn,
                          int n4)
{
    const int i = blockIdx.x * blockDim.x + threadIdx.x;
    if (i >= n4) return;
    const float a0 = __ldg(&attn[0]);
    const float a1 = __ldg(&attn[1]);
    float4 x = __ldg(&s0[i]);
    float4 y = __ldg(&s1[i]);
    out[i] = make_float4(a0 * x.x + a1 * y.x, a0 * x.y + a1 * y.y,
                         a0 * x.z + a1 * y.z, a0 * x.w + a1 * y.w);
}

// ----------------------------- semantic attention weights (paper, M=2) -------------
__global__ void sem_attn_k(const float* __restrict__ colsum, const float* __restrict__ q,
                           float* __restrict__ attn)
{
    __shared__ float r0[128], r1[128];
    const int t = threadIdx.x;  // 128 threads
    const float qv = q[t];
    r0[t] = qv * colsum[t];
    r1[t] = qv * colsum[128 + t];
    __syncthreads();
    for (int s = 64; s > 0; s >>= 1) {
        if (t < s) { r0[t] += r0[t + s]; r1[t] += r1[t + s]; }
        __syncthreads();
    }
    if (t == 0) {
        const float s0 = r0[0] / (float)NP;
        const float s1 = r1[0] / (float)NP;
        const float m = fmaxf(s0, s1);
        const float e0 = __expf(s0 - m), e1 = __expf(s1 - m);
        const float inv = 1.f / (e0 + e1);
        attn[0] = e0 * inv;
        attn[1] = e1 * inv;
    }
}

// ----------------------------- final linear: out[40000,16] -------------------------
__global__ __launch_bounds__(256)
void final_lin_k(const float* __restrict__ x, const float* __restrict__ W,
                 const float* __restrict__ b, float* __restrict__ out)
{
    __shared__ float Ws[128 * NCLS];
    for (int i = threadIdx.x; i < 128 * NCLS; i += blockDim.x) Ws[i] = W[i];
    __syncthreads();
    const int n = blockIdx.x * blockDim.x + threadIdx.x;
    if (n >= NP) return;
    float acc[NCLS];
#pragma unroll
    for (int c = 0; c < NCLS; c++) acc[c] = __ldg(&b[c]);
    const float4* xr = (const float4*)(x + (size_t)n * 128);
#pragma unroll
    for (int k4 = 0; k4 < 32; k4++) {
        float4 xv = __ldg(&xr[k4]);
        const float xs[4] = {xv.x, xv.y, xv.z, xv.w};
#pragma unroll
        for (int u = 0; u < 4; u++) {
            const int k = k4 * 4 + u;
#pragma unroll
            for (int c = 0; c < NCLS; c++)
                acc[c] = fmaf(xs[u], Ws[k * NCLS + c], acc[c]);
        }
    }
    float4* op = (float4*)(out + (size_t)n * NCLS);
#pragma unroll
    for (int c4 = 0; c4 < 4; c4++)
        op[c4] = make_float4(acc[c4 * 4], acc[c4 * 4 + 1], acc[c4 * 4 + 2], acc[c4 * 4 + 3]);
}

// ----------------------------- host orchestration ----------------------------------
extern "C" void kernel_launch(void* const* d_in, const int* in_sizes, int n_in,
                              void* d_out, int out_size)
{
    const float* x_author = (const float*)d_in[0];
    const float* x_paper  = (const float*)d_in[1];
    const float* Wa       = (const float*)d_in[2];
    const float* proj_w   = (const float*)d_in[3];
    const float* proj_b   = (const float*)d_in[4];
    const float* att_src  = (const float*)d_in[5];
    const float* att_dst  = (const float*)d_in[6];
    const float* klin_w   = (const float*)d_in[7];
    const float* klin_b   = (const float*)d_in[8];
    const float* q        = (const float*)d_in[9];
    const float* lin_w    = (const float*)d_in[10];
    const float* lin_b    = (const float*)d_in[11];
    const int*   ei_w     = (const int*)d_in[12];
    const int*   ei_wb    = (const int*)d_in[13];
    const int*   ei_c     = (const int*)d_in[14];
    float* out = (float*)d_out;

    float *auth0, *auth1, *pap0, *pap1, *xh_a, *xh_p, *asrc, *adst;
    float *escr, *denom, *aggP0, *aggP1, *colsum, *attn, *zbias;
    cudaGetSymbolAddress((void**)&auth0, g_auth0);
    cudaGetSymbolAddress((void**)&auth1, g_auth1);
    cudaGetSymbolAddress((void**)&pap0, g_pap0);
    cudaGetSymbolAddress((void**)&pap1, g_pap1);
    cudaGetSymbolAddress((void**)&xh_a, g_xh_a);
    cudaGetSymbolAddress((void**)&xh_p, g_xh_p);
    cudaGetSymbolAddress((void**)&asrc, g_asrc);
    cudaGetSymbolAddress((void**)&adst, g_adst);
    cudaGetSymbolAddress((void**)&escr, g_escr);
    cudaGetSymbolAddress((void**)&denom, g_denom);
    cudaGetSymbolAddress((void**)&aggP0, g_aggP0);
    cudaGetSymbolAddress((void**)&aggP1, g_aggP1);
    cudaGetSymbolAddress((void**)&colsum, g_colsum);
    cudaGetSymbolAddress((void**)&attn, g_attn);
    cudaGetSymbolAddress((void**)&zbias, g_zbias);

    // Type-alignment projection: author 64 -> 128 (no bias)
    sgemm_k<0><<<(NA + 127) / 128, 256>>>(x_author, Wa, zbias, auth0, nullptr, NA, 64);

    const float* cur_a = auth0;
    const float* cur_p = x_paper;
    float* next_a = auth1;
    float* next_p = pap0;

    for (int l = 0; l < 2; l++) {
        // Per-node-type projections -> xh
        sgemm_k<0><<<(NA + 127) / 128, 256>>>(
            cur_a, proj_w + (size_t)(l * 2 + 0) * 128 * 128,
            proj_b + (l * 2 + 0) * 128, xh_a, nullptr, NA, 128);
        sgemm_k<0><<<(NP + 127) / 128, 256>>>(
            cur_p, proj_w + (size_t)(l * 2 + 1) * 128 * 128,
            proj_b + (l * 2 + 1) * 128, xh_p, nullptr, NP, 128);

        struct ET { const int* ei; const float* xs; const float* xd; int ns; int nd; float* agg; };
        const ET et[3] = {
            { ei_w,  xh_a, xh_p, NA, NP, aggP0  },   // writes: author -> paper
            { ei_wb, xh_p, xh_a, NP, NA, next_a },   // written_by: paper -> author
            { ei_c,  xh_p, xh_p, NP, NP, aggP1  },   // cites: paper -> paper
        };

        for (int e = 0; e < 3; e++) {
            const float* av = att_src + (size_t)(l * 3 + e) * 128;
            const float* dv = att_dst + (size_t)(l * 3 + e) * 128;
            att_scores_k<<<(et[e].ns * 8 + 255) / 256, 256>>>(et[e].xs, av, asrc, et[e].ns);
            att_scores_k<<<(et[e].nd * 8 + 255) / 256, 256>>>(et[e].xd, dv, adst, et[e].nd);
            cudaMemsetAsync(denom, 0, (size_t)et[e].nd * 8 * sizeof(float));
            edge_passA<<<(EE + 255) / 256, 256>>>(et[e].ei, asrc, adst, escr, denom);
            cudaMemsetAsync(et[e].agg, 0, (size_t)et[e].nd * 128 * sizeof(float));
            edge_passB<<<(EE * 32 + 255) / 256, 256>>>(et[e].ei, et[e].xs, escr, denom, et[e].agg);
            relu4_k<<<(et[e].nd * 32 + 255) / 256, 256>>>((float4*)et[e].agg, et[e].nd * 32);
        }

        // Semantic attention over paper metapaths [writes, cites].
        // (author has a single metapath -> softmax == 1 -> next_a already final;
        //  inter-layer ReLU is a no-op on convex combos of ReLU'd aggregates.)
        cudaMemsetAsync(colsum, 0, 2 * 128 * sizeof(float));
        sgemm_k<1><<<(NP + 127) / 128, 256>>>(
            aggP0, klin_w + (size_t)l * 128 * 128, klin_b + l * 128,
            nullptr, colsum, NP, 128);
        sgemm_k<1><<<(NP + 127) / 128, 256>>>(
            aggP1, klin_w + (size_t)l * 128 * 128, klin_b + l * 128,
            nullptr, colsum + 128, NP, 128);
        sem_attn_k<<<1, 128>>>(colsum, q + l * 128, attn);
        combine_k<<<(NP * 32 + 255) / 256, 256>>>(
            (float4*)next_p, (const float4*)aggP0, (const float4*)aggP1, attn, NP * 32);

        // ping-pong
        cur_a = next_a;
        next_a = (cur_a == auth1) ? auth0 : auth1;
        cur_p = next_p;
        next_p = (cur_p == pap0) ? pap1 : pap0;
    }

    final_lin_k<<<(NP + 255) / 256, 256>>>(cur_p, lin_w, lin_b, out);
}